// round 3
// baseline (speedup 1.0000x reference)
#include <cuda_runtime.h>
#include <math.h>

#define HEADS    16
#define HEAD_DIM 64
#define DIM      1024
#define INNER    1024          // HEADS * HEAD_DIM
#define BATCH    2
#define SEQ      2048
#define ROWS     (BATCH * SEQ) // 4096
#define QKV_N    (3 * INNER)   // 3072

// Scratch (no cudaMalloc allowed anywhere)
__device__ float g_qkv [(size_t)ROWS * QKV_N];  // 48 MB
__device__ float g_attn[(size_t)ROWS * INNER];  // 16 MB
__device__ float g_res [(size_t)ROWS * DIM];    // 16 MB

// ---------------------------------------------------------------------------
// SGEMM: C[M,N] = A[M,K] @ B[K,N]  (+ bias[col] + resid[row,col] if non-null)
// 128x128 block tile, BK=8, 256 threads, 8x8 register tile per thread.
// M,N multiples of 128; K multiple of 8 (true for all calls here).
// ---------------------------------------------------------------------------
__global__ __launch_bounds__(256) void sgemm_kernel(
    const float* __restrict__ A, const float* __restrict__ B, float* __restrict__ C,
    int M, int N, int K,
    const float* __restrict__ bias, const float* __restrict__ resid)
{
    __shared__ float As[8][128];
    __shared__ float Bs[8][128];

    const int tid = threadIdx.x;
    const int bm  = blockIdx.y * 128;
    const int bn  = blockIdx.x * 128;

    // Global load mapping: 1024 floats per tile per matrix, 1 float4/thread
    const int arow = tid >> 1;          // 0..127
    const int acol = (tid & 1) << 2;    // 0 or 4   (k-dim)
    const int brow = tid >> 5;          // 0..7     (k-dim)
    const int bcol = (tid & 31) << 2;   // 0..124

    const float* Ap = A + (size_t)(bm + arow) * K + acol;
    const float* Bp = B + (size_t)brow * N + bn + bcol;

    const int tx = (tid & 15) << 3;     // col offset of 8x8 tile
    const int ty = (tid >> 4) << 3;     // row offset of 8x8 tile

    float acc[8][8];
#pragma unroll
    for (int i = 0; i < 8; i++)
#pragma unroll
        for (int j = 0; j < 8; j++) acc[i][j] = 0.f;

    for (int k0 = 0; k0 < K; k0 += 8) {
        float4 a4 = *(const float4*)Ap;
        float4 b4 = *(const float4*)Bp;
        As[acol + 0][arow] = a4.x;
        As[acol + 1][arow] = a4.y;
        As[acol + 2][arow] = a4.z;
        As[acol + 3][arow] = a4.w;
        *(float4*)&Bs[brow][bcol] = b4;
        __syncthreads();

#pragma unroll
        for (int k = 0; k < 8; k++) {
            float ra[8], rb[8];
            *(float4*)&ra[0] = *(const float4*)&As[k][ty];
            *(float4*)&ra[4] = *(const float4*)&As[k][ty + 4];
            *(float4*)&rb[0] = *(const float4*)&Bs[k][tx];
            *(float4*)&rb[4] = *(const float4*)&Bs[k][tx + 4];
#pragma unroll
            for (int i = 0; i < 8; i++)
#pragma unroll
                for (int j = 0; j < 8; j++)
                    acc[i][j] = fmaf(ra[i], rb[j], acc[i][j]);
        }
        __syncthreads();
        Ap += 8;
        Bp += (size_t)8 * N;
    }

#pragma unroll
    for (int i = 0; i < 8; i++) {
        const int row = bm + ty + i;
        float* Cp = C + (size_t)row * N + bn + tx;
#pragma unroll
        for (int j = 0; j < 8; j += 4) {
            float4 v;
            v.x = acc[i][j + 0]; v.y = acc[i][j + 1];
            v.z = acc[i][j + 2]; v.w = acc[i][j + 3];
            if (bias) {
                float4 bi = *(const float4*)(bias + bn + tx + j);
                v.x += bi.x; v.y += bi.y; v.z += bi.z; v.w += bi.w;
            }
            if (resid) {
                float4 r = *(const float4*)(resid + (size_t)row * N + bn + tx + j);
                v.x += r.x; v.y += r.y; v.z += r.z; v.w += r.w;
            }
            *(float4*)(Cp + j) = v;
        }
    }
}

// ---------------------------------------------------------------------------
// Attention: one query row per thread (q,o in registers), online softmax,
// K/V tiles of 32 rows staged in smem. Grid: (SEQ/128, BATCH*HEADS).
// qkv layout per row: [q(0..1023) | k(1024..2047) | v(2048..3071)], head h at +h*64
// ---------------------------------------------------------------------------
__global__ __launch_bounds__(128) void attn_kernel(
    const float* __restrict__ qkv, float* __restrict__ out)
{
    const int bh = blockIdx.y;
    const int b  = bh >> 4;          // / HEADS
    const int h  = bh & 15;
    const int q_idx = blockIdx.x * 128 + threadIdx.x;
    const int row0  = b * SEQ;
    const float scale = 0.125f;      // 1/sqrt(64)

    __shared__ float Ks[32][HEAD_DIM];
    __shared__ float Vs[32][HEAD_DIM];

    float q[HEAD_DIM];
    {
        const float* qp = qkv + (size_t)(row0 + q_idx) * QKV_N + h * HEAD_DIM;
#pragma unroll
        for (int d = 0; d < HEAD_DIM; d += 4) {
            float4 t = *(const float4*)(qp + d);
            q[d] = t.x * scale; q[d + 1] = t.y * scale;
            q[d + 2] = t.z * scale; q[d + 3] = t.w * scale;
        }
    }
    float o[HEAD_DIM];
#pragma unroll
    for (int d = 0; d < HEAD_DIM; d++) o[d] = 0.f;
    float m = -1e30f, l = 0.f;

    const int r = threadIdx.x >> 2;           // 0..31 (tile row to load)
    const int c = (threadIdx.x & 3) << 4;     // 0,16,32,48

    for (int k0 = 0; k0 < SEQ; k0 += 32) {
        __syncthreads();
        {
            const float* kp = qkv + (size_t)(row0 + k0 + r) * QKV_N + INNER + h * HEAD_DIM + c;
            const float* vp = kp + INNER;
#pragma unroll
            for (int i = 0; i < 16; i += 4) {
                *(float4*)&Ks[r][c + i] = *(const float4*)(kp + i);
                *(float4*)&Vs[r][c + i] = *(const float4*)(vp + i);
            }
        }
        __syncthreads();

        float s[32];
#pragma unroll
        for (int j = 0; j < 32; j++) {
            float a = 0.f;
#pragma unroll
            for (int d = 0; d < HEAD_DIM; d += 4) {
                float4 kv = *(const float4*)&Ks[j][d];   // uniform addr -> broadcast
                a = fmaf(q[d], kv.x, a);
                a = fmaf(q[d + 1], kv.y, a);
                a = fmaf(q[d + 2], kv.z, a);
                a = fmaf(q[d + 3], kv.w, a);
            }
            s[j] = a;
        }

        float nm = m;
#pragma unroll
        for (int j = 0; j < 32; j++) nm = fmaxf(nm, s[j]);
        const float corr = __expf(m - nm);
        m = nm;
        l *= corr;
#pragma unroll
        for (int d = 0; d < HEAD_DIM; d++) o[d] *= corr;

#pragma unroll
        for (int j = 0; j < 32; j++) {
            const float p = __expf(s[j] - m);
            l += p;
#pragma unroll
            for (int d = 0; d < HEAD_DIM; d += 4) {
                float4 vv = *(const float4*)&Vs[j][d];   // uniform addr -> broadcast
                o[d]     = fmaf(p, vv.x, o[d]);
                o[d + 1] = fmaf(p, vv.y, o[d + 1]);
                o[d + 2] = fmaf(p, vv.z, o[d + 2]);
                o[d + 3] = fmaf(p, vv.w, o[d + 3]);
            }
        }
    }

    const float inv = 1.f / l;
    float* op = out + (size_t)(row0 + q_idx) * INNER + h * HEAD_DIM;
#pragma unroll
    for (int d = 0; d < HEAD_DIM; d += 4) {
        float4 t;
        t.x = o[d] * inv; t.y = o[d + 1] * inv;
        t.z = o[d + 2] * inv; t.w = o[d + 3] * inv;
        *(float4*)(op + d) = t;
    }
}

// ---------------------------------------------------------------------------
// LayerNorm over last dim (1024). One block (256 threads) per row.
// ---------------------------------------------------------------------------
__global__ __launch_bounds__(256) void ln_kernel(
    const float* __restrict__ res, const float* __restrict__ gamma,
    const float* __restrict__ beta, float* __restrict__ out)
{
    const int row = blockIdx.x;
    const int tid = threadIdx.x;
    const float* rp = res + (size_t)row * DIM;

    float4 v = *(const float4*)(rp + tid * 4);
    float s  = v.x + v.y + v.z + v.w;
    float ss = v.x * v.x + v.y * v.y + v.z * v.z + v.w * v.w;

#pragma unroll
    for (int off = 16; off; off >>= 1) {
        s  += __shfl_xor_sync(0xffffffffu, s, off);
        ss += __shfl_xor_sync(0xffffffffu, ss, off);
    }
    __shared__ float red[18];
    const int w = tid >> 5, lane = tid & 31;
    if (lane == 0) { red[w] = s; red[8 + w] = ss; }
    __syncthreads();
    if (tid == 0) {
        float ts = 0.f, tss = 0.f;
#pragma unroll
        for (int i = 0; i < 8; i++) { ts += red[i]; tss += red[8 + i]; }
        red[16] = ts * (1.f / DIM);
        red[17] = tss * (1.f / DIM);
    }
    __syncthreads();
    const float mean = red[16];
    const float var  = red[17] - mean * mean;
    const float rstd = rsqrtf(var + 1e-5f);

    const int cidx = tid * 4;
    float4 g = *(const float4*)(gamma + cidx);
    float4 bb = *(const float4*)(beta + cidx);
    float4 ov;
    ov.x = (v.x - mean) * rstd * g.x + bb.x;
    ov.y = (v.y - mean) * rstd * g.y + bb.y;
    ov.z = (v.z - mean) * rstd * g.z + bb.z;
    ov.w = (v.w - mean) * rstd * g.w + bb.w;
    *(float4*)(out + (size_t)row * DIM + cidx) = ov;
}

// ---------------------------------------------------------------------------
extern "C" void kernel_launch(void* const* d_in, const int* in_sizes, int n_in,
                              void* d_out, int out_size)
{
    (void)in_sizes; (void)n_in; (void)out_size;
    const float* x     = (const float*)d_in[0];
    const float* w_qkv = (const float*)d_in[1];
    const float* w_out = (const float*)d_in[2];
    const float* b_out = (const float*)d_in[3];
    const float* gamma = (const float*)d_in[4];
    const float* beta  = (const float*)d_in[5];
    float* out = (float*)d_out;

    float *qkv, *attn, *res;
    cudaGetSymbolAddress((void**)&qkv,  g_qkv);
    cudaGetSymbolAddress((void**)&attn, g_attn);
    cudaGetSymbolAddress((void**)&res,  g_res);

    // 1) QKV projection: [4096,1024] @ [1024,3072]
    dim3 g1(QKV_N / 128, ROWS / 128);
    sgemm_kernel<<<g1, 256>>>(x, w_qkv, qkv, ROWS, QKV_N, DIM, nullptr, nullptr);

    // 2) Attention per (batch, head)
    dim3 g2(SEQ / 128, BATCH * HEADS);
    attn_kernel<<<g2, 128>>>(qkv, attn);

    // 3) Out projection + bias + residual: [4096,1024] @ [1024,1024]
    dim3 g3(DIM / 128, ROWS / 128);
    sgemm_kernel<<<g3, 256>>>(attn, w_out, res, ROWS, DIM, DIM, b_out, x);

    // 4) LayerNorm
    ln_kernel<<<ROWS, 256>>>(res, gamma, beta, out);
}

// round 7
// speedup vs baseline: 2.1271x; 2.1271x over previous
#include <cuda_runtime.h>
#include <cuda_bf16.h>
#include <math.h>
#include <stdint.h>

#define HEADS    16
#define HEAD_DIM 64
#define DIM      1024
#define INNER    1024
#define BATCH    2
#define SEQ      2048
#define ROWS     4096
#define QKV_N    3072

// ---------------- scratch (no allocs allowed) ----------------
__device__ float         g_qkv[(size_t)ROWS * QKV_N];   // 48 MB
__device__ float         g_res[(size_t)ROWS * DIM];     // 16 MB
__device__ __nv_bfloat16 g_ahi[(size_t)ROWS * DIM];     // 8 MB
__device__ __nv_bfloat16 g_alo[(size_t)ROWS * DIM];     // 8 MB
__device__ __nv_bfloat16 g_bhi[(size_t)QKV_N * DIM];    // 6 MB
__device__ __nv_bfloat16 g_blo[(size_t)QKV_N * DIM];    // 6 MB

// ---------------- PTX helpers (plain sm_103-legal only) ----------------
__device__ __forceinline__ uint32_t smem_u32(const void* p) {
    uint32_t a;
    asm("{ .reg .u64 t; cvta.to.shared.u64 t, %1; cvt.u32.u64 %0, t; }" : "=r"(a) : "l"(p));
    return a;
}
__device__ __forceinline__ void cp16(uint32_t s, const void* g) {
    asm volatile("cp.async.cg.shared.global [%0], [%1], 16;" :: "r"(s), "l"(g));
}
#define CP_COMMIT() asm volatile("cp.async.commit_group;" ::: "memory")
#define CP_WAIT(n)  asm volatile("cp.async.wait_group %0;" :: "n"(n) : "memory")

__device__ __forceinline__ void ldsm4(uint32_t& r0, uint32_t& r1, uint32_t& r2, uint32_t& r3,
                                      uint32_t a) {
    asm volatile("ldmatrix.sync.aligned.m8n8.x4.shared.b16 {%0,%1,%2,%3}, [%4];"
                 : "=r"(r0), "=r"(r1), "=r"(r2), "=r"(r3) : "r"(a));
}
__device__ __forceinline__ void mma16816(float* d, const uint32_t* a, uint32_t b0, uint32_t b1) {
    asm volatile(
        "mma.sync.aligned.m16n8k16.row.col.f32.bf16.bf16.f32 "
        "{%0,%1,%2,%3}, {%4,%5,%6,%7}, {%8,%9}, {%0,%1,%2,%3};"
        : "+f"(d[0]), "+f"(d[1]), "+f"(d[2]), "+f"(d[3])
        : "r"(a[0]), "r"(a[1]), "r"(a[2]), "r"(a[3]), "r"(b0), "r"(b1));
}

// ---------------------------------------------------------------------------
// Prep: fp32 -> bf16 hi/lo elementwise (same layout). n4 = total/4.
// ---------------------------------------------------------------------------
__global__ __launch_bounds__(256) void split_fp32(
    const float* __restrict__ X, __nv_bfloat16* __restrict__ H,
    __nv_bfloat16* __restrict__ L, int n4)
{
    int i = blockIdx.x * 256 + threadIdx.x;
    if (i >= n4) return;
    float4 v = ((const float4*)X)[i];
    union { __nv_bfloat16 b[4]; uint2 u; } ph, pl;
    float f[4] = {v.x, v.y, v.z, v.w};
#pragma unroll
    for (int j = 0; j < 4; j++) {
        __nv_bfloat16 h = __float2bfloat16(f[j]);
        ph.b[j] = h;
        pl.b[j] = __float2bfloat16(f[j] - __bfloat162float(h));
    }
    ((uint2*)H)[i] = ph.u;
    ((uint2*)L)[i] = pl.u;
}

// ---------------------------------------------------------------------------
// Prep: W[K,N] fp32 -> W^T hi/lo bf16 [N,K]  (32x32 smem tiles)
// ---------------------------------------------------------------------------
__global__ void tsplit(const float* __restrict__ W, __nv_bfloat16* __restrict__ TH,
                       __nv_bfloat16* __restrict__ TL, int K, int N)
{
    __shared__ float t[32][33];
    int n0 = blockIdx.x * 32, k0 = blockIdx.y * 32;
    int tx = threadIdx.x, ty = threadIdx.y;  // (32, 8)
#pragma unroll
    for (int i = 0; i < 32; i += 8)
        t[ty + i][tx] = W[(size_t)(k0 + ty + i) * N + n0 + tx];
    __syncthreads();
#pragma unroll
    for (int i = 0; i < 32; i += 8) {
        float v = t[tx][ty + i];
        __nv_bfloat16 h = __float2bfloat16(v);
        size_t oidx = (size_t)(n0 + ty + i) * K + k0 + tx;
        TH[oidx] = h;
        TL[oidx] = __float2bfloat16(v - __bfloat162float(h));
    }
}

// ---------------------------------------------------------------------------
// mma.sync bf16x3 GEMM: C[M,N] = A[M,K] @ B_T[N,K]^T  (fp32 out)
// Block 128x128, 8 warps of 64x32, BK=32, 2-stage cp.async pipeline.
// SMEM rows padded to 80B -> conflict-free ldmatrix.
// ---------------------------------------------------------------------------
#define BM 128
#define BN 128
#define BKC 32
#define ROWB 80                         // padded row bytes (32 bf16 + 16B pad)
#define TILE_BYTES (128 * ROWB)         // 10240 per matrix-half
#define STAGE_BYTES (4 * TILE_BYTES)    // Ahi, Alo, Bhi, Blo
#define GEMM_SMEM (2 * STAGE_BYTES + 256)

struct GemmArgs {
    const __nv_bfloat16 *Ahi, *Alo, *Bhi, *Blo;
};

__global__ __launch_bounds__(256) void gemm_mma(
    const __nv_bfloat16* __restrict__ Ahi, const __nv_bfloat16* __restrict__ Alo,
    const __nv_bfloat16* __restrict__ Bhi, const __nv_bfloat16* __restrict__ Blo,
    float* __restrict__ C, int K, int N,
    const float* __restrict__ bias, const float* __restrict__ resid)
{
    extern __shared__ char dsm[];
    const int tid  = threadIdx.x;
    const int wid  = tid >> 5;
    const int lane = tid & 31;
    const int bm   = blockIdx.y * BM;
    const int bn   = blockIdx.x * BN;

    const uint32_t sb = (smem_u32(dsm) + 127u) & ~127u;

    // per-thread load mapping: chunks c = tid, tid+256 (512 16B-chunks per tile)
    const int r0 = tid >> 2,        e0 = (tid & 3) * 8;
    const int r1 = (tid + 256) >> 2, e1 = ((tid + 256) & 3) * 8;
    const uint32_t s0 = r0 * ROWB + (tid & 3) * 16;
    const uint32_t s1 = r1 * ROWB + ((tid + 256) & 3) * 16;

    const size_t gA0 = (size_t)(bm + r0) * K + e0;
    const size_t gA1 = (size_t)(bm + r1) * K + e1;
    const size_t gB0 = (size_t)(bn + r0) * K + e0;
    const size_t gB1 = (size_t)(bn + r1) * K + e1;

    float acc[4][4][4];
#pragma unroll
    for (int i = 0; i < 4; i++)
#pragma unroll
        for (int j = 0; j < 4; j++)
#pragma unroll
            for (int q = 0; q < 4; q++) acc[i][j][q] = 0.f;

    const int nch = K / BKC;

#define LOAD_STAGE(kc, st) do {                                                 \
    uint32_t s = sb + (st) * STAGE_BYTES;                                       \
    int ko = (kc) * BKC;                                                        \
    cp16(s + s0,                  Ahi + gA0 + ko);                              \
    cp16(s + s1,                  Ahi + gA1 + ko);                              \
    cp16(s + TILE_BYTES + s0,     Alo + gA0 + ko);                              \
    cp16(s + TILE_BYTES + s1,     Alo + gA1 + ko);                              \
    cp16(s + 2 * TILE_BYTES + s0, Bhi + gB0 + ko);                              \
    cp16(s + 2 * TILE_BYTES + s1, Bhi + gB1 + ko);                              \
    cp16(s + 3 * TILE_BYTES + s0, Blo + gB0 + ko);                              \
    cp16(s + 3 * TILE_BYTES + s1, Blo + gB1 + ko);                              \
} while (0)

    LOAD_STAGE(0, 0);
    CP_COMMIT();

    const int wm = (wid & 1) * 64;
    const int wn = (wid >> 1) * 32;

    // ldmatrix base offsets (within a tile)
    const uint32_t a_off = (uint32_t)(wm + (lane & 15)) * ROWB + ((lane >> 4) << 3) * 2;
    const uint32_t b_off = (uint32_t)(wn + (lane & 7) + ((lane >> 4) << 3)) * ROWB +
                           (((lane >> 3) & 1) << 3) * 2;

    for (int kc = 0; kc < nch; kc++) {
        const int st = kc & 1;
        if (kc + 1 < nch) {
            LOAD_STAGE(kc + 1, st ^ 1);
            CP_COMMIT();
            CP_WAIT(1);
        } else {
            CP_WAIT(0);
        }
        __syncthreads();

        const uint32_t sAhi = sb + st * STAGE_BYTES;
        const uint32_t sAlo = sAhi + TILE_BYTES;
        const uint32_t sBhi = sAhi + 2 * TILE_BYTES;
        const uint32_t sBlo = sAhi + 3 * TILE_BYTES;

#pragma unroll
        for (int ks = 0; ks < 2; ks++) {
            const uint32_t kb = ks * 32;  // 16 bf16 = 32 bytes
            uint32_t ah[4][4], al[4][4], bh[8], bl[8];
#pragma unroll
            for (int mf = 0; mf < 4; mf++)
                ldsm4(ah[mf][0], ah[mf][1], ah[mf][2], ah[mf][3],
                      sAhi + a_off + kb + mf * (16 * ROWB));
#pragma unroll
            for (int mf = 0; mf < 4; mf++)
                ldsm4(al[mf][0], al[mf][1], al[mf][2], al[mf][3],
                      sAlo + a_off + kb + mf * (16 * ROWB));
            ldsm4(bh[0], bh[1], bh[2], bh[3], sBhi + b_off + kb);
            ldsm4(bh[4], bh[5], bh[6], bh[7], sBhi + b_off + kb + 16 * ROWB);
            ldsm4(bl[0], bl[1], bl[2], bl[3], sBlo + b_off + kb);
            ldsm4(bl[4], bl[5], bl[6], bl[7], sBlo + b_off + kb + 16 * ROWB);

#pragma unroll
            for (int mf = 0; mf < 4; mf++)
#pragma unroll
                for (int nf = 0; nf < 4; nf++)
                    mma16816(acc[mf][nf], ah[mf], bh[nf * 2], bh[nf * 2 + 1]);
#pragma unroll
            for (int mf = 0; mf < 4; mf++)
#pragma unroll
                for (int nf = 0; nf < 4; nf++)
                    mma16816(acc[mf][nf], ah[mf], bl[nf * 2], bl[nf * 2 + 1]);
#pragma unroll
            for (int mf = 0; mf < 4; mf++)
#pragma unroll
                for (int nf = 0; nf < 4; nf++)
                    mma16816(acc[mf][nf], al[mf], bh[nf * 2], bh[nf * 2 + 1]);
        }
        __syncthreads();
    }

    // ---------------- epilogue: direct fp32 stores (+bias +resid) ----------------
#pragma unroll
    for (int mf = 0; mf < 4; mf++) {
        const int row = bm + wm + mf * 16 + (lane >> 2);
#pragma unroll
        for (int nf = 0; nf < 4; nf++) {
            const int col = bn + wn + nf * 8 + 2 * (lane & 3);
            float2 v0 = make_float2(acc[mf][nf][0], acc[mf][nf][1]);
            float2 v1 = make_float2(acc[mf][nf][2], acc[mf][nf][3]);
            if (bias) {
                float2 bi = *(const float2*)(bias + col);
                v0.x += bi.x; v0.y += bi.y;
                v1.x += bi.x; v1.y += bi.y;
            }
            if (resid) {
                float2 ra = *(const float2*)(resid + (size_t)row * N + col);
                float2 rb = *(const float2*)(resid + (size_t)(row + 8) * N + col);
                v0.x += ra.x; v0.y += ra.y;
                v1.x += rb.x; v1.y += rb.y;
            }
            *(float2*)(C + (size_t)row * N + col) = v0;
            *(float2*)(C + (size_t)(row + 8) * N + col) = v1;
        }
    }
#undef LOAD_STAGE
}

// ---------------------------------------------------------------------------
// Attention (SIMT, fp32): 1 query/thread, online softmax, 32-row K/V tiles.
// Writes output directly as bf16 hi/lo (A operand of the out projection).
// ---------------------------------------------------------------------------
__global__ __launch_bounds__(128) void attn_kernel(
    const float* __restrict__ qkv,
    __nv_bfloat16* __restrict__ ohi, __nv_bfloat16* __restrict__ olo)
{
    const int bh = blockIdx.y;
    const int b  = bh >> 4;
    const int h  = bh & 15;
    const int q_idx = blockIdx.x * 128 + threadIdx.x;
    const int row0  = b * SEQ;
    const float scale = 0.125f;

    __shared__ float Ks[32][HEAD_DIM];
    __shared__ float Vs[32][HEAD_DIM];

    float q[HEAD_DIM];
    {
        const float* qp = qkv + (size_t)(row0 + q_idx) * QKV_N + h * HEAD_DIM;
#pragma unroll
        for (int d = 0; d < HEAD_DIM; d += 4) {
            float4 t = *(const float4*)(qp + d);
            q[d] = t.x * scale; q[d + 1] = t.y * scale;
            q[d + 2] = t.z * scale; q[d + 3] = t.w * scale;
        }
    }
    float o[HEAD_DIM];
#pragma unroll
    for (int d = 0; d < HEAD_DIM; d++) o[d] = 0.f;
    float m = -1e30f, l = 0.f;

    const int r = threadIdx.x >> 2;
    const int c = (threadIdx.x & 3) << 4;

    for (int k0 = 0; k0 < SEQ; k0 += 32) {
        __syncthreads();
        {
            const float* kp = qkv + (size_t)(row0 + k0 + r) * QKV_N + INNER + h * HEAD_DIM + c;
            const float* vp = kp + INNER;
#pragma unroll
            for (int i = 0; i < 16; i += 4) {
                *(float4*)&Ks[r][c + i] = *(const float4*)(kp + i);
                *(float4*)&Vs[r][c + i] = *(const float4*)(vp + i);
            }
        }
        __syncthreads();

        float s[32];
#pragma unroll
        for (int j = 0; j < 32; j++) {
            float a = 0.f;
#pragma unroll
            for (int d = 0; d < HEAD_DIM; d += 4) {
                float4 kv = *(const float4*)&Ks[j][d];
                a = fmaf(q[d], kv.x, a);
                a = fmaf(q[d + 1], kv.y, a);
                a = fmaf(q[d + 2], kv.z, a);
                a = fmaf(q[d + 3], kv.w, a);
            }
            s[j] = a;
        }

        float nm = m;
#pragma unroll
        for (int j = 0; j < 32; j++) nm = fmaxf(nm, s[j]);
        const float corr = __expf(m - nm);
        m = nm;
        l *= corr;
#pragma unroll
        for (int d = 0; d < HEAD_DIM; d++) o[d] *= corr;

#pragma unroll
        for (int j = 0; j < 32; j++) {
            const float p = __expf(s[j] - m);
            l += p;
#pragma unroll
            for (int d = 0; d < HEAD_DIM; d += 4) {
                float4 vv = *(const float4*)&Vs[j][d];
                o[d]     = fmaf(p, vv.x, o[d]);
                o[d + 1] = fmaf(p, vv.y, o[d + 1]);
                o[d + 2] = fmaf(p, vv.z, o[d + 2]);
                o[d + 3] = fmaf(p, vv.w, o[d + 3]);
            }
        }
    }

    const float inv = 1.f / l;
    __nv_bfloat16* ph = ohi + (size_t)(row0 + q_idx) * INNER + h * HEAD_DIM;
    __nv_bfloat16* pl = olo + (size_t)(row0 + q_idx) * INNER + h * HEAD_DIM;
#pragma unroll
    for (int d = 0; d < HEAD_DIM; d += 2) {
        float v0 = o[d] * inv, v1 = o[d + 1] * inv;
        __nv_bfloat16 h0 = __float2bfloat16(v0);
        __nv_bfloat16 h1 = __float2bfloat16(v1);
        __nv_bfloat162 hh; hh.x = h0; hh.y = h1;
        *(__nv_bfloat162*)(ph + d) = hh;
        __nv_bfloat162 ll;
        ll.x = __float2bfloat16(v0 - __bfloat162float(h0));
        ll.y = __float2bfloat16(v1 - __bfloat162float(h1));
        *(__nv_bfloat162*)(pl + d) = ll;
    }
}

// ---------------------------------------------------------------------------
// LayerNorm over last dim (1024). One block (256 threads) per row.
// ---------------------------------------------------------------------------
__global__ __launch_bounds__(256) void ln_kernel(
    const float* __restrict__ res, const float* __restrict__ gamma,
    const float* __restrict__ beta, float* __restrict__ out)
{
    const int row = blockIdx.x;
    const int tid = threadIdx.x;
    const float* rp = res + (size_t)row * DIM;

    float4 v = *(const float4*)(rp + tid * 4);
    float s  = v.x + v.y + v.z + v.w;
    float ss = v.x * v.x + v.y * v.y + v.z * v.z + v.w * v.w;

#pragma unroll
    for (int off = 16; off; off >>= 1) {
        s  += __shfl_xor_sync(0xffffffffu, s, off);
        ss += __shfl_xor_sync(0xffffffffu, ss, off);
    }
    __shared__ float red[18];
    const int w = tid >> 5, lane = tid & 31;
    if (lane == 0) { red[w] = s; red[8 + w] = ss; }
    __syncthreads();
    if (tid == 0) {
        float ts = 0.f, tss = 0.f;
#pragma unroll
        for (int i = 0; i < 8; i++) { ts += red[i]; tss += red[8 + i]; }
        red[16] = ts * (1.f / DIM);
        red[17] = tss * (1.f / DIM);
    }
    __syncthreads();
    const float mean = red[16];
    const float var  = red[17] - mean * mean;
    const float rstd = rsqrtf(var + 1e-5f);

    const int cidx = tid * 4;
    float4 g  = *(const float4*)(gamma + cidx);
    float4 bb = *(const float4*)(beta + cidx);
    float4 ov;
    ov.x = (v.x - mean) * rstd * g.x + bb.x;
    ov.y = (v.y - mean) * rstd * g.y + bb.y;
    ov.z = (v.z - mean) * rstd * g.z + bb.z;
    ov.w = (v.w - mean) * rstd * g.w + bb.w;
    *(float4*)(out + (size_t)row * DIM + cidx) = ov;
}

// ---------------------------------------------------------------------------
extern "C" void kernel_launch(void* const* d_in, const int* in_sizes, int n_in,
                              void* d_out, int out_size)
{
    (void)in_sizes; (void)n_in; (void)out_size;
    const float* x     = (const float*)d_in[0];
    const float* w_qkv = (const float*)d_in[1];
    const float* w_out = (const float*)d_in[2];
    const float* b_out = (const float*)d_in[3];
    const float* gamma = (const float*)d_in[4];
    const float* beta  = (const float*)d_in[5];
    float* out = (float*)d_out;

    float *qkv, *res;
    __nv_bfloat16 *ahi, *alo, *bhi, *blo;
    cudaGetSymbolAddress((void**)&qkv, g_qkv);
    cudaGetSymbolAddress((void**)&res, g_res);
    cudaGetSymbolAddress((void**)&ahi, g_ahi);
    cudaGetSymbolAddress((void**)&alo, g_alo);
    cudaGetSymbolAddress((void**)&bhi, g_bhi);
    cudaGetSymbolAddress((void**)&blo, g_blo);

    cudaFuncSetAttribute(gemm_mma, cudaFuncAttributeMaxDynamicSharedMemorySize, GEMM_SMEM);

    // 0) x -> bf16 hi/lo
    split_fp32<<<(ROWS * DIM / 4 + 255) / 256, 256>>>(x, ahi, alo, ROWS * DIM / 4);
    // 0b) w_qkv [1024,3072] -> transposed hi/lo [3072,1024]
    tsplit<<<dim3(QKV_N / 32, DIM / 32), dim3(32, 8)>>>(w_qkv, bhi, blo, DIM, QKV_N);

    // 1) QKV projection on tensor cores (mma.sync)
    gemm_mma<<<dim3(QKV_N / BN, ROWS / BM), 256, GEMM_SMEM>>>(
        ahi, alo, bhi, blo, qkv, DIM, QKV_N, nullptr, nullptr);

    // 2) Attention (writes bf16 hi/lo for next GEMM)
    attn_kernel<<<dim3(SEQ / 128, BATCH * HEADS), 128>>>(qkv, ahi, alo);

    // 2b) w_out [1024,1024] -> transposed hi/lo
    tsplit<<<dim3(DIM / 32, DIM / 32), dim3(32, 8)>>>(w_out, bhi, blo, DIM, DIM);

    // 3) Out projection + bias + residual on tensor cores
    gemm_mma<<<dim3(DIM / BN, ROWS / BM), 256, GEMM_SMEM>>>(
        ahi, alo, bhi, blo, res, DIM, DIM, b_out, x);

    // 4) LayerNorm
    ln_kernel<<<ROWS, 256>>>(res, gamma, beta, out);
}

// round 9
// speedup vs baseline: 4.7858x; 2.2499x over previous
#include <cuda_runtime.h>
#include <cuda_bf16.h>
#include <math.h>
#include <stdint.h>

#define HEADS    16
#define HEAD_DIM 64
#define DIM      1024
#define INNER    1024
#define BATCH    2
#define SEQ      2048
#define ROWS     4096
#define QKV_N    3072

// ---------------- scratch (no allocs allowed) ----------------
__device__ float         g_qkv[(size_t)ROWS * QKV_N];   // 48 MB
__device__ float         g_res[(size_t)ROWS * DIM];     // 16 MB
__device__ __nv_bfloat16 g_ahi[(size_t)ROWS * DIM];     // x hi -> attn-out hi
__device__ __nv_bfloat16 g_alo[(size_t)ROWS * DIM];
__device__ __nv_bfloat16 g_bhi[(size_t)QKV_N * DIM];    // weights hi
__device__ __nv_bfloat16 g_blo[(size_t)QKV_N * DIM];
__device__ __nv_bfloat16 g_qhi[(size_t)ROWS * DIM];     // scaled q
__device__ __nv_bfloat16 g_qlo[(size_t)ROWS * DIM];
__device__ __nv_bfloat16 g_khi[(size_t)ROWS * DIM];     // [bh][key][d]
__device__ __nv_bfloat16 g_klo[(size_t)ROWS * DIM];
__device__ __nv_bfloat16 g_vthi[(size_t)ROWS * DIM];    // [bh][d][key]
__device__ __nv_bfloat16 g_vtlo[(size_t)ROWS * DIM];

// ---------------- PTX helpers (plain sm_103-legal) ----------------
__device__ __forceinline__ uint32_t smem_u32(const void* p) {
    uint32_t a;
    asm("{ .reg .u64 t; cvta.to.shared.u64 t, %1; cvt.u32.u64 %0, t; }" : "=r"(a) : "l"(p));
    return a;
}
__device__ __forceinline__ void cp16(uint32_t s, const void* g) {
    asm volatile("cp.async.cg.shared.global [%0], [%1], 16;" :: "r"(s), "l"(g));
}
#define CP_COMMIT() asm volatile("cp.async.commit_group;" ::: "memory")
#define CP_WAIT(n)  asm volatile("cp.async.wait_group %0;" :: "n"(n) : "memory")

__device__ __forceinline__ void ldsm4(uint32_t& r0, uint32_t& r1, uint32_t& r2, uint32_t& r3,
                                      uint32_t a) {
    asm volatile("ldmatrix.sync.aligned.m8n8.x4.shared.b16 {%0,%1,%2,%3}, [%4];"
                 : "=r"(r0), "=r"(r1), "=r"(r2), "=r"(r3) : "r"(a));
}
__device__ __forceinline__ void mma16816(float* d, const uint32_t* a, uint32_t b0, uint32_t b1) {
    asm volatile(
        "mma.sync.aligned.m16n8k16.row.col.f32.bf16.bf16.f32 "
        "{%0,%1,%2,%3}, {%4,%5,%6,%7}, {%8,%9}, {%0,%1,%2,%3};"
        : "+f"(d[0]), "+f"(d[1]), "+f"(d[2]), "+f"(d[3])
        : "r"(a[0]), "r"(a[1]), "r"(a[2]), "r"(a[3]), "r"(b0), "r"(b1));
}
__device__ __forceinline__ void split2(float a, float b, uint32_t& hi, uint32_t& lo) {
    __nv_bfloat16 ha = __float2bfloat16(a), hb = __float2bfloat16(b);
    __nv_bfloat162 H; H.x = ha; H.y = hb;
    __nv_bfloat162 L;
    L.x = __float2bfloat16(a - __bfloat162float(ha));
    L.y = __float2bfloat16(b - __bfloat162float(hb));
    hi = *(uint32_t*)&H;
    lo = *(uint32_t*)&L;
}

// ---------------------------------------------------------------------------
// Prep: fp32 -> bf16 hi/lo elementwise. n4 = total/4.
// ---------------------------------------------------------------------------
__global__ __launch_bounds__(256) void split_fp32(
    const float* __restrict__ X, __nv_bfloat16* __restrict__ H,
    __nv_bfloat16* __restrict__ L, int n4)
{
    int i = blockIdx.x * 256 + threadIdx.x;
    if (i >= n4) return;
    float4 v = ((const float4*)X)[i];
    union { __nv_bfloat16 b[4]; uint2 u; } ph, pl;
    float f[4] = {v.x, v.y, v.z, v.w};
#pragma unroll
    for (int j = 0; j < 4; j++) {
        __nv_bfloat16 h = __float2bfloat16(f[j]);
        ph.b[j] = h;
        pl.b[j] = __float2bfloat16(f[j] - __bfloat162float(h));
    }
    ((uint2*)H)[i] = ph.u;
    ((uint2*)L)[i] = pl.u;
}

// ---------------------------------------------------------------------------
// Prep: W[K,N] fp32 -> W^T hi/lo bf16 [N,K]
// ---------------------------------------------------------------------------
__global__ void tsplit(const float* __restrict__ W, __nv_bfloat16* __restrict__ TH,
                       __nv_bfloat16* __restrict__ TL, int K, int N)
{
    __shared__ float t[32][33];
    int n0 = blockIdx.x * 32, k0 = blockIdx.y * 32;
    int tx = threadIdx.x, ty = threadIdx.y;  // (32, 8)
#pragma unroll
    for (int i = 0; i < 32; i += 8)
        t[ty + i][tx] = W[(size_t)(k0 + ty + i) * N + n0 + tx];
    __syncthreads();
#pragma unroll
    for (int i = 0; i < 32; i += 8) {
        float v = t[tx][ty + i];
        __nv_bfloat16 h = __float2bfloat16(v);
        size_t oidx = (size_t)(n0 + ty + i) * K + k0 + tx;
        TH[oidx] = h;
        TL[oidx] = __float2bfloat16(v - __bfloat162float(h));
    }
}

// ---------------------------------------------------------------------------
// Repack qkv fp32 -> q (scaled 0.125) hi/lo [row][1024] and k hi/lo [bh][key][d]
// ---------------------------------------------------------------------------
__global__ __launch_bounds__(256) void qk_repack(
    const float* __restrict__ qkv,
    __nv_bfloat16* __restrict__ qhi, __nv_bfloat16* __restrict__ qlo,
    __nv_bfloat16* __restrict__ khi, __nv_bfloat16* __restrict__ klo)
{
    int idx = blockIdx.x * 256 + threadIdx.x;     // 1M quads
    int row = idx >> 8;
    int c   = (idx & 255) << 2;

    // q
    {
        float4 v = *(const float4*)(qkv + (size_t)row * QKV_N + c);
        union { __nv_bfloat16 b[4]; uint2 u; } ph, pl;
        float f[4] = {v.x * 0.125f, v.y * 0.125f, v.z * 0.125f, v.w * 0.125f};
#pragma unroll
        for (int j = 0; j < 4; j++) {
            __nv_bfloat16 h = __float2bfloat16(f[j]);
            ph.b[j] = h;
            pl.b[j] = __float2bfloat16(f[j] - __bfloat162float(h));
        }
        *(uint2*)(qhi + (size_t)row * DIM + c) = ph.u;
        *(uint2*)(qlo + (size_t)row * DIM + c) = pl.u;
    }
    // k
    {
        float4 v = *(const float4*)(qkv + (size_t)row * QKV_N + INNER + c);
        union { __nv_bfloat16 b[4]; uint2 u; } ph, pl;
        float f[4] = {v.x, v.y, v.z, v.w};
#pragma unroll
        for (int j = 0; j < 4; j++) {
            __nv_bfloat16 h = __float2bfloat16(f[j]);
            ph.b[j] = h;
            pl.b[j] = __float2bfloat16(f[j] - __bfloat162float(h));
        }
        int b = row >> 11, key = row & 2047, h = c >> 6, d = c & 63;
        size_t o = ((size_t)(b * HEADS + h) << 17) + key * 64 + d;
        *(uint2*)(khi + o) = ph.u;
        *(uint2*)(klo + o) = pl.u;
    }
}

// ---------------------------------------------------------------------------
// V transpose: qkv v-part -> vt hi/lo [bh][dim][key]
// ---------------------------------------------------------------------------
__global__ __launch_bounds__(256) void v_transpose(
    const float* __restrict__ qkv,
    __nv_bfloat16* __restrict__ vthi, __nv_bfloat16* __restrict__ vtlo)
{
    __shared__ float t[64][65];
    const int bh = blockIdx.y, b = bh >> 4, h = bh & 15;
    const int key0 = blockIdx.x * 64;
    const int tid = threadIdx.x;
#pragma unroll
    for (int i = 0; i < 16; i++) {
        int c = tid + i * 256;
        int ky = c >> 6, d = c & 63;
        t[ky][d] = qkv[(size_t)(b * SEQ + key0 + ky) * QKV_N + 2048 + h * 64 + d];
    }
    __syncthreads();
#pragma unroll
    for (int i = 0; i < 16; i++) {
        int c = tid + i * 256;
        int d = c >> 6, ky = c & 63;
        float v = t[ky][d];
        __nv_bfloat16 hv = __float2bfloat16(v);
        size_t o = ((size_t)bh << 17) + (size_t)d * SEQ + key0 + ky;
        vthi[o] = hv;
        vtlo[o] = __float2bfloat16(v - __bfloat162float(hv));
    }
}

// ---------------------------------------------------------------------------
// Flash attention on mma.sync bf16 (split hi/lo). Block: (b,h) x 128 queries,
// 8 warps x 16 q-rows. Key tiles of 64, double-buffered cp.async.
// Writes output as bf16 hi/lo (A operand of out-projection).
// ---------------------------------------------------------------------------
#define AT_ROWB  144
#define AT_TILE  (64 * AT_ROWB)       // 9216
#define AT_STAGE (4 * AT_TILE)        // Khi,Klo,Vthi,Vtlo
#define AT_SMEM  (2 * AT_STAGE + 128)

__global__ __launch_bounds__(256) void attn_mma(
    const __nv_bfloat16* __restrict__ qhi, const __nv_bfloat16* __restrict__ qlo,
    const __nv_bfloat16* __restrict__ khi, const __nv_bfloat16* __restrict__ klo,
    const __nv_bfloat16* __restrict__ vthi, const __nv_bfloat16* __restrict__ vtlo,
    __nv_bfloat16* __restrict__ ohi, __nv_bfloat16* __restrict__ olo)
{
    extern __shared__ char dsm[];
    const int tid  = threadIdx.x;
    const int wid  = tid >> 5;
    const int lane = tid & 31;
    const int g    = lane >> 2;
    const int t    = lane & 3;
    const int bh   = blockIdx.y;
    const int b    = bh >> 4;
    const int h    = bh & 15;
    const int row0 = b * SEQ + blockIdx.x * 128;

    const uint32_t sb = (smem_u32(dsm) + 127u) & ~127u;

    // ---- stage Q (hi at sb, lo at sb+18432), ldmatrix to regs ----
    {
        const uint32_t sQhi = sb, sQlo = sb + 128 * AT_ROWB;
#pragma unroll
        for (int i = 0; i < 4; i++) {
            int c = tid + i * 256;           // 1024 chunks
            int r = c >> 3, ch = c & 7;
            size_t gq = (size_t)(row0 + r) * DIM + h * 64 + ch * 8;
            cp16(sQhi + r * AT_ROWB + ch * 16, qhi + gq);
            cp16(sQlo + r * AT_ROWB + ch * 16, qlo + gq);
        }
        CP_COMMIT();
        CP_WAIT(0);
        __syncthreads();
    }
    uint32_t qh[4][4], ql[4][4];
    {
        const uint32_t qoff = (uint32_t)(wid * 16 + (lane & 15)) * AT_ROWB +
                              ((lane >> 4) << 3) * 2;
#pragma unroll
        for (int ks = 0; ks < 4; ks++) {
            ldsm4(qh[ks][0], qh[ks][1], qh[ks][2], qh[ks][3], sb + qoff + ks * 32);
            ldsm4(ql[ks][0], ql[ks][1], ql[ks][2], ql[ks][3],
                  sb + 128 * AT_ROWB + qoff + ks * 32);
        }
    }
    __syncthreads();

    float o[8][4];
#pragma unroll
    for (int i = 0; i < 8; i++)
#pragma unroll
        for (int j = 0; j < 4; j++) o[i][j] = 0.f;
    float m0 = -1e30f, m1 = -1e30f, l0 = 0.f, l1 = 0.f;

    const __nv_bfloat16* kb_hi = khi + ((size_t)bh << 17);
    const __nv_bfloat16* kb_lo = klo + ((size_t)bh << 17);
    const __nv_bfloat16* vb_hi = vthi + ((size_t)bh << 17);
    const __nv_bfloat16* vb_lo = vtlo + ((size_t)bh << 17);

#define LOADKV(kt, st) do {                                                     \
    uint32_t s = sb + (st) * AT_STAGE;                                          \
    int key0 = (kt) * 64;                                                       \
    _Pragma("unroll")                                                           \
    for (int i = 0; i < 2; i++) {                                               \
        int c = tid + i * 256;                                                  \
        int r = c >> 3, ch = c & 7;                                             \
        uint32_t so = r * AT_ROWB + ch * 16;                                    \
        cp16(s + so,               kb_hi + (size_t)(key0 + r) * 64 + ch * 8);   \
        cp16(s + AT_TILE + so,     kb_lo + (size_t)(key0 + r) * 64 + ch * 8);   \
        cp16(s + 2 * AT_TILE + so, vb_hi + (size_t)r * SEQ + key0 + ch * 8);    \
        cp16(s + 3 * AT_TILE + so, vb_lo + (size_t)r * SEQ + key0 + ch * 8);    \
    }                                                                           \
} while (0)

    const uint32_t boff = (uint32_t)((lane & 7) + ((lane >> 4) << 3)) * AT_ROWB +
                          (((lane >> 3) & 1) << 3) * 2;

    LOADKV(0, 0);
    CP_COMMIT();

    const int NT = SEQ / 64;
    for (int kt = 0; kt < NT; kt++) {
        const int st = kt & 1;
        if (kt + 1 < NT) {
            LOADKV(kt + 1, st ^ 1);
            CP_COMMIT();
            CP_WAIT(1);
        } else {
            CP_WAIT(0);
        }
        __syncthreads();

        const uint32_t sKh = sb + st * AT_STAGE;
        const uint32_t sKl = sKh + AT_TILE;
        const uint32_t sVh = sKh + 2 * AT_TILE;
        const uint32_t sVl = sKh + 3 * AT_TILE;

        // ---- S = Q K^T (3-term split) ----
        float s[8][4];
#pragma unroll
        for (int i = 0; i < 8; i++)
#pragma unroll
            for (int j = 0; j < 4; j++) s[i][j] = 0.f;

#pragma unroll
        for (int ks = 0; ks < 4; ks++) {
            uint32_t kh4[4][4], kl4[4][4];
#pragma unroll
            for (int kb = 0; kb < 4; kb++) {
                ldsm4(kh4[kb][0], kh4[kb][1], kh4[kb][2], kh4[kb][3],
                      sKh + boff + kb * (16 * AT_ROWB) + ks * 32);
                ldsm4(kl4[kb][0], kl4[kb][1], kl4[kb][2], kl4[kb][3],
                      sKl + boff + kb * (16 * AT_ROWB) + ks * 32);
            }
#pragma unroll
            for (int kb = 0; kb < 4; kb++) {
                mma16816(s[2 * kb],     qh[ks], kh4[kb][0], kh4[kb][1]);
                mma16816(s[2 * kb + 1], qh[ks], kh4[kb][2], kh4[kb][3]);
                mma16816(s[2 * kb],     qh[ks], kl4[kb][0], kl4[kb][1]);
                mma16816(s[2 * kb + 1], qh[ks], kl4[kb][2], kl4[kb][3]);
                mma16816(s[2 * kb],     ql[ks], kh4[kb][0], kh4[kb][1]);
                mma16816(s[2 * kb + 1], ql[ks], kh4[kb][2], kh4[kb][3]);
            }
        }

        // ---- online softmax (fp32 regs) ----
        float mx0 = -1e30f, mx1 = -1e30f;
#pragma unroll
        for (int nf = 0; nf < 8; nf++) {
            mx0 = fmaxf(mx0, fmaxf(s[nf][0], s[nf][1]));
            mx1 = fmaxf(mx1, fmaxf(s[nf][2], s[nf][3]));
        }
        mx0 = fmaxf(mx0, __shfl_xor_sync(0xffffffffu, mx0, 1));
        mx0 = fmaxf(mx0, __shfl_xor_sync(0xffffffffu, mx0, 2));
        mx1 = fmaxf(mx1, __shfl_xor_sync(0xffffffffu, mx1, 1));
        mx1 = fmaxf(mx1, __shfl_xor_sync(0xffffffffu, mx1, 2));
        const float nm0 = fmaxf(m0, mx0), nm1 = fmaxf(m1, mx1);
        const float c0 = __expf(m0 - nm0), c1 = __expf(m1 - nm1);
#pragma unroll
        for (int nf = 0; nf < 8; nf++) {
            o[nf][0] *= c0; o[nf][1] *= c0;
            o[nf][2] *= c1; o[nf][3] *= c1;
        }
        float rs0 = 0.f, rs1 = 0.f;
#pragma unroll
        for (int nf = 0; nf < 8; nf++) {
            s[nf][0] = __expf(s[nf][0] - nm0); rs0 += s[nf][0];
            s[nf][1] = __expf(s[nf][1] - nm0); rs0 += s[nf][1];
            s[nf][2] = __expf(s[nf][2] - nm1); rs1 += s[nf][2];
            s[nf][3] = __expf(s[nf][3] - nm1); rs1 += s[nf][3];
        }
        rs0 += __shfl_xor_sync(0xffffffffu, rs0, 1);
        rs0 += __shfl_xor_sync(0xffffffffu, rs0, 2);
        rs1 += __shfl_xor_sync(0xffffffffu, rs1, 1);
        rs1 += __shfl_xor_sync(0xffffffffu, rs1, 2);
        l0 = l0 * c0 + rs0;
        l1 = l1 * c1 + rs1;
        m0 = nm0; m1 = nm1;

        // ---- O += P V (3-term split) ----
#pragma unroll
        for (int kk = 0; kk < 4; kk++) {
            uint32_t ph[4], pl[4];
            split2(s[2 * kk][0],     s[2 * kk][1],     ph[0], pl[0]);
            split2(s[2 * kk][2],     s[2 * kk][3],     ph[1], pl[1]);
            split2(s[2 * kk + 1][0], s[2 * kk + 1][1], ph[2], pl[2]);
            split2(s[2 * kk + 1][2], s[2 * kk + 1][3], ph[3], pl[3]);

            uint32_t vh4[4][4], vl4[4][4];
#pragma unroll
            for (int db = 0; db < 4; db++) {
                ldsm4(vh4[db][0], vh4[db][1], vh4[db][2], vh4[db][3],
                      sVh + boff + db * (16 * AT_ROWB) + kk * 32);
                ldsm4(vl4[db][0], vl4[db][1], vl4[db][2], vl4[db][3],
                      sVl + boff + db * (16 * AT_ROWB) + kk * 32);
            }
#pragma unroll
            for (int db = 0; db < 4; db++) {
                mma16816(o[2 * db],     ph, vh4[db][0], vh4[db][1]);
                mma16816(o[2 * db + 1], ph, vh4[db][2], vh4[db][3]);
                mma16816(o[2 * db],     pl, vh4[db][0], vh4[db][1]);
                mma16816(o[2 * db + 1], pl, vh4[db][2], vh4[db][3]);
                mma16816(o[2 * db],     ph, vl4[db][0], vl4[db][1]);
                mma16816(o[2 * db + 1], ph, vl4[db][2], vl4[db][3]);
            }
        }
        __syncthreads();
    }
#undef LOADKV

    // ---- epilogue: o/l -> bf16 hi/lo ----
    const float inv0 = 1.f / l0, inv1 = 1.f / l1;
    const int row_a = row0 + wid * 16 + g;
    const int row_b = row_a + 8;
#pragma unroll
    for (int nf = 0; nf < 8; nf++) {
        const int col = h * 64 + nf * 8 + 2 * t;
        uint32_t hh, ll;
        split2(o[nf][0] * inv0, o[nf][1] * inv0, hh, ll);
        *(uint32_t*)(ohi + (size_t)row_a * DIM + col) = hh;
        *(uint32_t*)(olo + (size_t)row_a * DIM + col) = ll;
        split2(o[nf][2] * inv1, o[nf][3] * inv1, hh, ll);
        *(uint32_t*)(ohi + (size_t)row_b * DIM + col) = hh;
        *(uint32_t*)(olo + (size_t)row_b * DIM + col) = ll;
    }
}

// ---------------------------------------------------------------------------
// mma.sync bf16x3 GEMM (unchanged from R7): C = A[M,K] @ B_T[N,K]^T
// ---------------------------------------------------------------------------
#define BM 128
#define BN 128
#define BKC 32
#define ROWB 80
#define TILE_BYTES (128 * ROWB)
#define STAGE_BYTES (4 * TILE_BYTES)
#define GEMM_SMEM (2 * STAGE_BYTES + 256)

__global__ __launch_bounds__(256) void gemm_mma(
    const __nv_bfloat16* __restrict__ Ahi, const __nv_bfloat16* __restrict__ Alo,
    const __nv_bfloat16* __restrict__ Bhi, const __nv_bfloat16* __restrict__ Blo,
    float* __restrict__ C, int K, int N,
    const float* __restrict__ bias, const float* __restrict__ resid)
{
    extern __shared__ char dsm[];
    const int tid  = threadIdx.x;
    const int wid  = tid >> 5;
    const int lane = tid & 31;
    const int bm   = blockIdx.y * BM;
    const int bn   = blockIdx.x * BN;

    const uint32_t sb = (smem_u32(dsm) + 127u) & ~127u;

    const int r0 = tid >> 2,         e0 = (tid & 3) * 8;
    const int r1 = (tid + 256) >> 2, e1 = ((tid + 256) & 3) * 8;
    const uint32_t s0 = r0 * ROWB + (tid & 3) * 16;
    const uint32_t s1 = r1 * ROWB + ((tid + 256) & 3) * 16;

    const size_t gA0 = (size_t)(bm + r0) * K + e0;
    const size_t gA1 = (size_t)(bm + r1) * K + e1;
    const size_t gB0 = (size_t)(bn + r0) * K + e0;
    const size_t gB1 = (size_t)(bn + r1) * K + e1;

    float acc[4][4][4];
#pragma unroll
    for (int i = 0; i < 4; i++)
#pragma unroll
        for (int j = 0; j < 4; j++)
#pragma unroll
            for (int q = 0; q < 4; q++) acc[i][j][q] = 0.f;

    const int nch = K / BKC;

#define LOAD_STAGE(kc, st) do {                                                 \
    uint32_t s = sb + (st) * STAGE_BYTES;                                       \
    int ko = (kc) * BKC;                                                        \
    cp16(s + s0,                  Ahi + gA0 + ko);                              \
    cp16(s + s1,                  Ahi + gA1 + ko);                              \
    cp16(s + TILE_BYTES + s0,     Alo + gA0 + ko);                              \
    cp16(s + TILE_BYTES + s1,     Alo + gA1 + ko);                              \
    cp16(s + 2 * TILE_BYTES + s0, Bhi + gB0 + ko);                              \
    cp16(s + 2 * TILE_BYTES + s1, Bhi + gB1 + ko);                              \
    cp16(s + 3 * TILE_BYTES + s0, Blo + gB0 + ko);                              \
    cp16(s + 3 * TILE_BYTES + s1, Blo + gB1 + ko);                              \
} while (0)

    LOAD_STAGE(0, 0);
    CP_COMMIT();

    const int wm = (wid & 1) * 64;
    const int wn = (wid >> 1) * 32;

    const uint32_t a_off = (uint32_t)(wm + (lane & 15)) * ROWB + ((lane >> 4) << 3) * 2;
    const uint32_t b_off = (uint32_t)(wn + (lane & 7) + ((lane >> 4) << 3)) * ROWB +
                           (((lane >> 3) & 1) << 3) * 2;

    for (int kc = 0; kc < nch; kc++) {
        const int st = kc & 1;
        if (kc + 1 < nch) {
            LOAD_STAGE(kc + 1, st ^ 1);
            CP_COMMIT();
            CP_WAIT(1);
        } else {
            CP_WAIT(0);
        }
        __syncthreads();

        const uint32_t sAhi = sb + st * STAGE_BYTES;
        const uint32_t sAlo = sAhi + TILE_BYTES;
        const uint32_t sBhi = sAhi + 2 * TILE_BYTES;
        const uint32_t sBlo = sAhi + 3 * TILE_BYTES;

#pragma unroll
        for (int ks = 0; ks < 2; ks++) {
            const uint32_t kb = ks * 32;
            uint32_t ah[4][4], al[4][4], bh[8], bl[8];
#pragma unroll
            for (int mf = 0; mf < 4; mf++)
                ldsm4(ah[mf][0], ah[mf][1], ah[mf][2], ah[mf][3],
                      sAhi + a_off + kb + mf * (16 * ROWB));
#pragma unroll
            for (int mf = 0; mf < 4; mf++)
                ldsm4(al[mf][0], al[mf][1], al[mf][2], al[mf][3],
                      sAlo + a_off + kb + mf * (16 * ROWB));
            ldsm4(bh[0], bh[1], bh[2], bh[3], sBhi + b_off + kb);
            ldsm4(bh[4], bh[5], bh[6], bh[7], sBhi + b_off + kb + 16 * ROWB);
            ldsm4(bl[0], bl[1], bl[2], bl[3], sBlo + b_off + kb);
            ldsm4(bl[4], bl[5], bl[6], bl[7], sBlo + b_off + kb + 16 * ROWB);

#pragma unroll
            for (int mf = 0; mf < 4; mf++)
#pragma unroll
                for (int nf = 0; nf < 4; nf++)
                    mma16816(acc[mf][nf], ah[mf], bh[nf * 2], bh[nf * 2 + 1]);
#pragma unroll
            for (int mf = 0; mf < 4; mf++)
#pragma unroll
                for (int nf = 0; nf < 4; nf++)
                    mma16816(acc[mf][nf], ah[mf], bl[nf * 2], bl[nf * 2 + 1]);
#pragma unroll
            for (int mf = 0; mf < 4; mf++)
#pragma unroll
                for (int nf = 0; nf < 4; nf++)
                    mma16816(acc[mf][nf], al[mf], bh[nf * 2], bh[nf * 2 + 1]);
        }
        __syncthreads();
    }

#pragma unroll
    for (int mf = 0; mf < 4; mf++) {
        const int row = bm + wm + mf * 16 + (lane >> 2);
#pragma unroll
        for (int nf = 0; nf < 4; nf++) {
            const int col = bn + wn + nf * 8 + 2 * (lane & 3);
            float2 v0 = make_float2(acc[mf][nf][0], acc[mf][nf][1]);
            float2 v1 = make_float2(acc[mf][nf][2], acc[mf][nf][3]);
            if (bias) {
                float2 bi = *(const float2*)(bias + col);
                v0.x += bi.x; v0.y += bi.y;
                v1.x += bi.x; v1.y += bi.y;
            }
            if (resid) {
                float2 ra = *(const float2*)(resid + (size_t)row * N + col);
                float2 rb = *(const float2*)(resid + (size_t)(row + 8) * N + col);
                v0.x += ra.x; v0.y += ra.y;
                v1.x += rb.x; v1.y += rb.y;
            }
            *(float2*)(C + (size_t)row * N + col) = v0;
            *(float2*)(C + (size_t)(row + 8) * N + col) = v1;
        }
    }
#undef LOAD_STAGE
}

// ---------------------------------------------------------------------------
// LayerNorm over last dim (1024). One block (256 threads) per row.
// ---------------------------------------------------------------------------
__global__ __launch_bounds__(256) void ln_kernel(
    const float* __restrict__ res, const float* __restrict__ gamma,
    const float* __restrict__ beta, float* __restrict__ out)
{
    const int row = blockIdx.x;
    const int tid = threadIdx.x;
    const float* rp = res + (size_t)row * DIM;

    float4 v = *(const float4*)(rp + tid * 4);
    float s  = v.x + v.y + v.z + v.w;
    float ss = v.x * v.x + v.y * v.y + v.z * v.z + v.w * v.w;

#pragma unroll
    for (int off = 16; off; off >>= 1) {
        s  += __shfl_xor_sync(0xffffffffu, s, off);
        ss += __shfl_xor_sync(0xffffffffu, ss, off);
    }
    __shared__ float red[18];
    const int w = tid >> 5, lane = tid & 31;
    if (lane == 0) { red[w] = s; red[8 + w] = ss; }
    __syncthreads();
    if (tid == 0) {
        float ts = 0.f, tss = 0.f;
#pragma unroll
        for (int i = 0; i < 8; i++) { ts += red[i]; tss += red[8 + i]; }
        red[16] = ts * (1.f / DIM);
        red[17] = tss * (1.f / DIM);
    }
    __syncthreads();
    const float mean = red[16];
    const float var  = red[17] - mean * mean;
    const float rstd = rsqrtf(var + 1e-5f);

    const int cidx = tid * 4;
    float4 g  = *(const float4*)(gamma + cidx);
    float4 bb = *(const float4*)(beta + cidx);
    float4 ov;
    ov.x = (v.x - mean) * rstd * g.x + bb.x;
    ov.y = (v.y - mean) * rstd * g.y + bb.y;
    ov.z = (v.z - mean) * rstd * g.z + bb.z;
    ov.w = (v.w - mean) * rstd * g.w + bb.w;
    *(float4*)(out + (size_t)row * DIM + cidx) = ov;
}

// ---------------------------------------------------------------------------
extern "C" void kernel_launch(void* const* d_in, const int* in_sizes, int n_in,
                              void* d_out, int out_size)
{
    (void)in_sizes; (void)n_in; (void)out_size;
    const float* x     = (const float*)d_in[0];
    const float* w_qkv = (const float*)d_in[1];
    const float* w_out = (const float*)d_in[2];
    const float* b_out = (const float*)d_in[3];
    const float* gamma = (const float*)d_in[4];
    const float* beta  = (const float*)d_in[5];
    float* out = (float*)d_out;

    float *qkv, *res;
    __nv_bfloat16 *ahi, *alo, *bhi, *blo, *qhi, *qlo, *khi, *klo, *vthi, *vtlo;
    cudaGetSymbolAddress((void**)&qkv, g_qkv);
    cudaGetSymbolAddress((void**)&res, g_res);
    cudaGetSymbolAddress((void**)&ahi, g_ahi);
    cudaGetSymbolAddress((void**)&alo, g_alo);
    cudaGetSymbolAddress((void**)&bhi, g_bhi);
    cudaGetSymbolAddress((void**)&blo, g_blo);
    cudaGetSymbolAddress((void**)&qhi, g_qhi);
    cudaGetSymbolAddress((void**)&qlo, g_qlo);
    cudaGetSymbolAddress((void**)&khi, g_khi);
    cudaGetSymbolAddress((void**)&klo, g_klo);
    cudaGetSymbolAddress((void**)&vthi, g_vthi);
    cudaGetSymbolAddress((void**)&vtlo, g_vtlo);

    cudaFuncSetAttribute(gemm_mma, cudaFuncAttributeMaxDynamicSharedMemorySize, GEMM_SMEM);
    cudaFuncSetAttribute(attn_mma, cudaFuncAttributeMaxDynamicSharedMemorySize, AT_SMEM);

    // 0) x -> bf16 hi/lo ; w_qkv -> transposed hi/lo
    split_fp32<<<(ROWS * DIM / 4 + 255) / 256, 256>>>(x, ahi, alo, ROWS * DIM / 4);
    tsplit<<<dim3(QKV_N / 32, DIM / 32), dim3(32, 8)>>>(w_qkv, bhi, blo, DIM, QKV_N);

    // 1) QKV projection (tensor cores)
    gemm_mma<<<dim3(QKV_N / BN, ROWS / BM), 256, GEMM_SMEM>>>(
        ahi, alo, bhi, blo, qkv, DIM, QKV_N, nullptr, nullptr);

    // 2) repack q/k (scaled q) + transpose v
    qk_repack<<<ROWS * DIM / 4 / 256, 256>>>(qkv, qhi, qlo, khi, klo);
    v_transpose<<<dim3(SEQ / 64, BATCH * HEADS), 256>>>(qkv, vthi, vtlo);

    // 3) flash attention on tensor cores -> bf16 hi/lo output
    attn_mma<<<dim3(SEQ / 128, BATCH * HEADS), 256, AT_SMEM>>>(
        qhi, qlo, khi, klo, vthi, vtlo, ahi, alo);

    // 4) out projection + bias + residual
    tsplit<<<dim3(DIM / 32, DIM / 32), dim3(32, 8)>>>(w_out, bhi, blo, DIM, DIM);
    gemm_mma<<<dim3(DIM / BN, ROWS / BM), 256, GEMM_SMEM>>>(
        ahi, alo, bhi, blo, res, DIM, DIM, b_out, x);

    // 5) LayerNorm
    ln_kernel<<<ROWS, 256>>>(res, gamma, beta, out);
}